// round 7
// baseline (speedup 1.0000x reference)
#include <cuda_runtime.h>
#include <cuda_bf16.h>

#define NTHR  256
#define NWARP 8
#define NH    50
#define NNEG  10
#define NROWS 62
#define EDIM  128
#define EV4   32
#define EPS   1e-6f

__device__ __forceinline__ float dot4(float4 a, float4 b) {
    return a.x * b.x + a.y * b.y + a.z * b.z + a.w * b.w;
}
__device__ __forceinline__ float wredsum(float v) {
#pragma unroll
    for (int o = 16; o; o >>= 1) v += __shfl_xor_sync(0xffffffffu, v, o);
    return v;
}
__device__ __forceinline__ float wredmax(float v) {
#pragma unroll
    for (int o = 16; o; o >>= 1) v = fmaxf(v, __shfl_xor_sync(0xffffffffu, v, o));
    return v;
}

__global__ __launch_bounds__(NTHR, 8) void htne_kernel(
    const int*   __restrict__ s_nodes,
    const int*   __restrict__ t_nodes,
    const float* __restrict__ t_times,
    const int*   __restrict__ h_nodes,
    const float* __restrict__ h_times,
    const float* __restrict__ h_mask,
    const int*   __restrict__ n_nodes,
    const float* __restrict__ emb,
    const float* __restrict__ delta_w,
    float*       __restrict__ out)
{
    const int b    = blockIdx.x;
    const int tid  = threadIdx.x;
    const int wid  = tid >> 5;
    const int lane = tid & 31;

    __shared__ float his_s[NH][EDIM];    // 25.6 KB (staged histories)
    __shared__ float hbar_p[2][EDIM];    // 1 KB
    __shared__ float scal_s[64 * 4];     // [row][0:rr 1:rs 2:rt]  1 KB
    __shared__ int   nidx_s[NNEG];       // neg node indices for tail reload
    __shared__ float w_s[NH];
    __shared__ float nterm_s[NNEG];
    __shared__ float sc[4];              // 0:W 1:C 2:P 3:invS

    const float4* emb4 = (const float4*)emb;
    const int sidx = s_nodes[b];
    const int tidx = t_nodes[b];

    const int sub     = lane & 15;
    const int halfsel = lane >> 4;

    const float4 s4a = emb4[(size_t)sidx * EV4 + sub];
    const float4 s4b = emb4[(size_t)sidx * EV4 + sub + 16];
    const float4 t4a = emb4[(size_t)tidx * EV4 + sub];
    const float4 t4b = emb4[(size_t)tidx * EV4 + sub + 16];

    // ---- phase 1: uniform 62-row gather + STS(his) + 3 dots, 8 shfl per 2 rows ----
#pragma unroll
    for (int j = 0; j < 4; j++) {
        const int r = j * 16 + wid * 2 + halfsel;
        int node;
        if      (r < NH)  node = h_nodes[b * NH + r];
        else if (r < 60)  node = n_nodes[b * NNEG + (r - 50)];
        else if (r == 60) node = sidx;
        else              node = tidx;
        if (sub == 0 && r >= NH && r < 60) nidx_s[r - 50] = node;
        const float4* rowp = emb4 + (size_t)node * EV4;
        const float4 r0 = rowp[sub];
        const float4 r1 = rowp[sub + 16];
        if (r < NH) {
            float4* hs = (float4*)his_s[r];
            hs[sub]      = r0;
            hs[sub + 16] = r1;
        }
        float a  = dot4(r0, r0)  + dot4(r1, r1);
        float bb = dot4(r0, s4a) + dot4(r1, s4b);
        float c  = dot4(r0, t4a) + dot4(r1, t4b);
        a  += __shfl_xor_sync(0xffffffffu, a, 8);
        bb += __shfl_xor_sync(0xffffffffu, bb, 8);
        c  += __shfl_xor_sync(0xffffffffu, c, 8);
        a  += __shfl_xor_sync(0xffffffffu, a, 4);
        bb += __shfl_xor_sync(0xffffffffu, bb, 4);
        c  += __shfl_xor_sync(0xffffffffu, c, 4);
        const int g2 = (lane >> 2) & 3;
        float x = (g2 == 0) ? a : (g2 == 1) ? bb : c;
        x += __shfl_xor_sync(0xffffffffu, x, 2);
        x += __shfl_xor_sync(0xffffffffu, x, 1);
        if ((lane & 3) == 0 && g2 < 3 && r < NROWS)
            scal_s[r * 4 + g2] = x;
    }
    __syncthreads();

    // ---- softmax + weighted scalar reductions (warp 0) ----
    if (wid == 0) {
        const float src_sq = scal_s[60 * 4 + 0];
        const float tar_sq = scal_s[61 * 4 + 0];
        const float delta  = delta_w[sidx];
        const float ttime  = t_times[b];

        float logit[2], pal[2], dm[2];
        float m = -1e30f;
#pragma unroll
        for (int k = 0; k < 2; k++) {
            const int h = lane + 32 * k;
            if (h < NH) {
                const float hh = scal_s[h * 4 + 0];
                logit[k] = -(src_sq + hh - 2.0f * scal_s[h * 4 + 1]);
                pal[k]   = -(tar_sq + hh - 2.0f * scal_s[h * 4 + 2]);
                const float dt = fabsf(ttime - h_times[b * NH + h]);
                dm[k] = __expf(delta * dt) * h_mask[b * NH + h];
                m = fmaxf(m, logit[k]);
            }
        }
        m = wredmax(m);

        float S = 0.f, Wn = 0.f, Cn = 0.f, Pn = 0.f;
#pragma unroll
        for (int k = 0; k < 2; k++) {
            const int h = lane + 32 * k;
            if (h < NH) {
                const float e = __expf(logit[k] - m);
                const float w = e * dm[k];
                w_s[h] = w;
                S  += e;
                Wn += w;
                Cn += w * scal_s[h * 4 + 0];
                Pn += w * pal[k];
            }
        }
        S  += __shfl_xor_sync(0xffffffffu, S, 16);
        Wn += __shfl_xor_sync(0xffffffffu, Wn, 16);
        Cn += __shfl_xor_sync(0xffffffffu, Cn, 16);
        Pn += __shfl_xor_sync(0xffffffffu, Pn, 16);
        S  += __shfl_xor_sync(0xffffffffu, S, 8);
        Wn += __shfl_xor_sync(0xffffffffu, Wn, 8);
        Cn += __shfl_xor_sync(0xffffffffu, Cn, 8);
        Pn += __shfl_xor_sync(0xffffffffu, Pn, 8);
        const int g = lane >> 3;
        float x = (g == 0) ? S : (g == 1) ? Wn : (g == 2) ? Cn : Pn;
        x += __shfl_xor_sync(0xffffffffu, x, 4);
        x += __shfl_xor_sync(0xffffffffu, x, 2);
        x += __shfl_xor_sync(0xffffffffu, x, 1);
        const float Sv = __shfl_sync(0xffffffffu, x, 0);
        if (lane == 8)  sc[0] = x / Sv;      // W
        if (lane == 16) sc[1] = x / Sv;      // C
        if (lane == 24) sc[2] = x / Sv;      // P
        if (lane == 0)  sc[3] = 1.0f / Sv;   // invS
    }
    __syncthreads();

    // ---- hbar partials from smem-staged histories ----
    {
        const int e    = tid & (EDIM - 1);
        const int half = tid >> 7;
        const int h0   = half * 25;
        float acc = 0.f;
#pragma unroll 5
        for (int h = h0; h < h0 + 25; h++)
            acc += w_s[h] * his_s[h][e];
        hbar_p[half][e] = acc;
    }
    __syncthreads();

    // ---- tail: per-negative hbar.n (reload neg rows from hot gmem) ----
    {
        const float4 p0 = ((const float4*)hbar_p[0])[lane];
        const float4 p1 = ((const float4*)hbar_p[1])[lane];
        float4 hb4;
        hb4.x = p0.x + p1.x; hb4.y = p0.y + p1.y;
        hb4.z = p0.z + p1.z; hb4.w = p0.w + p1.w;

        const float Wv = sc[0], Cv = sc[1], invS = sc[3];
        const float ss = scal_s[60 * 4 + 0];

        {
            const int n = wid;
            const float4 ng = emb4[(size_t)nidx_s[n] * EV4 + lane];
            float hn = wredsum(dot4(hb4, ng));
            if (lane == 0) {
                const float nn = scal_s[(50 + n) * 4 + 0];
                const float sn = scal_s[(50 + n) * 4 + 1];
                const float n_mu = -(ss + nn - 2.0f * sn);
                const float nl   = n_mu - Cv - Wv * nn + 2.0f * invS * hn;
                nterm_s[n] = __logf(1.0f / (1.0f + __expf(nl)) + EPS);
            }
        }
        if (wid < NNEG - NWARP) {
            const int n = NWARP + wid;
            const float4 ng = emb4[(size_t)nidx_s[n] * EV4 + lane];
            float hn = wredsum(dot4(hb4, ng));
            if (lane == 0) {
                const float nn = scal_s[(50 + n) * 4 + 0];
                const float sn = scal_s[(50 + n) * 4 + 1];
                const float n_mu = -(ss + nn - 2.0f * sn);
                const float nl   = n_mu - Cv - Wv * nn + 2.0f * invS * hn;
                nterm_s[n] = __logf(1.0f / (1.0f + __expf(nl)) + EPS);
            }
        }
    }
    __syncthreads();

    if (tid == 0) {
        const float ss = scal_s[60 * 4 + 0];
        const float st = scal_s[60 * 4 + 2];
        const float tt = scal_s[61 * 4 + 0];
        const float p_mu     = -(ss + tt - 2.0f * st);
        const float p_lambda = p_mu + sc[2];
        const float pos_loss = -__logf(1.0f / (1.0f + __expf(-p_lambda)) + EPS);
        float neg_loss = 0.f;
#pragma unroll
        for (int n = 0; n < NNEG; n++) neg_loss += nterm_s[n];
        out[b] = pos_loss - neg_loss;
    }
}

extern "C" void kernel_launch(void* const* d_in, const int* in_sizes, int n_in,
                              void* d_out, int out_size)
{
    const int*   s_nodes = (const int*)  d_in[0];
    const int*   t_nodes = (const int*)  d_in[1];
    const float* t_times = (const float*)d_in[2];
    const int*   h_nodes = (const int*)  d_in[3];
    const float* h_times = (const float*)d_in[4];
    const float* h_mask  = (const float*)d_in[5];
    const int*   n_nodes = (const int*)  d_in[6];
    const float* emb     = (const float*)d_in[7];
    const float* delta_w = (const float*)d_in[8];
    float*       out     = (float*)d_out;

    const int B = in_sizes[0];
    htne_kernel<<<B, NTHR>>>(s_nodes, t_nodes, t_times, h_nodes, h_times,
                             h_mask, n_nodes, emb, delta_w, out);
}

// round 8
// speedup vs baseline: 1.0613x; 1.0613x over previous
#include <cuda_runtime.h>
#include <cuda_bf16.h>

#define NTHR  256
#define NWARP 8
#define NH    50
#define NNEG  10
#define NROWS 62
#define EDIM  128
#define EV4   32
#define EPS   1e-6f

__device__ __forceinline__ float dot4(float4 a, float4 b) {
    return a.x * b.x + a.y * b.y + a.z * b.z + a.w * b.w;
}
__device__ __forceinline__ float wredsum(float v) {
#pragma unroll
    for (int o = 16; o; o >>= 1) v += __shfl_xor_sync(0xffffffffu, v, o);
    return v;
}
__device__ __forceinline__ float wredmax(float v) {
#pragma unroll
    for (int o = 16; o; o >>= 1) v = fmaxf(v, __shfl_xor_sync(0xffffffffu, v, o));
    return v;
}

__global__ __launch_bounds__(NTHR, 8) void htne_kernel(
    const int*   __restrict__ s_nodes,
    const int*   __restrict__ t_nodes,
    const float* __restrict__ t_times,
    const int*   __restrict__ h_nodes,
    const float* __restrict__ h_times,
    const float* __restrict__ h_mask,
    const int*   __restrict__ n_nodes,
    const float* __restrict__ emb,
    const float* __restrict__ delta_w,
    float*       __restrict__ out)
{
    const int b    = blockIdx.x;
    const int tid  = threadIdx.x;
    const int wid  = tid >> 5;
    const int lane = tid & 31;

    __shared__ float4 hb_p[NWARP * 32];  // 4 KB: per-warp hbar partials
    __shared__ float  scal_s[64 * 4];    // [row][0:rr 1:rs 2:rt]  1 KB
    __shared__ int    idx_s[64];         // node index per row
    __shared__ float  w_s[NH];
    __shared__ float  nterm_s[NNEG];
    __shared__ float  sc[4];             // 0:W 1:C 2:P 3:invS

    const float4* emb4 = (const float4*)emb;
    const int sidx = s_nodes[b];
    const int tidx = t_nodes[b];

    const int sub     = lane & 15;
    const int halfsel = lane >> 4;

    const float4 s4a = emb4[(size_t)sidx * EV4 + sub];
    const float4 s4b = emb4[(size_t)sidx * EV4 + sub + 16];
    const float4 t4a = emb4[(size_t)tidx * EV4 + sub];
    const float4 t4b = emb4[(size_t)tidx * EV4 + sub + 16];

    // ---- phase 1: uniform 62-row gather + 3 dots per row, 8 shfl per 2 rows ----
#pragma unroll
    for (int j = 0; j < 4; j++) {
        const int r = j * 16 + wid * 2 + halfsel;
        int node;
        if      (r < NH)  node = h_nodes[b * NH + r];
        else if (r < 60)  node = n_nodes[b * NNEG + (r - 50)];
        else if (r == 60) node = sidx;
        else              node = tidx;
        if (sub == 0 && r < NROWS) idx_s[r] = node;
        const float4* rowp = emb4 + (size_t)node * EV4;
        const float4 r0 = rowp[sub];
        const float4 r1 = rowp[sub + 16];
        float a  = dot4(r0, r0)  + dot4(r1, r1);
        float bb = dot4(r0, s4a) + dot4(r1, s4b);
        float c  = dot4(r0, t4a) + dot4(r1, t4b);
        a  += __shfl_xor_sync(0xffffffffu, a, 8);
        bb += __shfl_xor_sync(0xffffffffu, bb, 8);
        c  += __shfl_xor_sync(0xffffffffu, c, 8);
        a  += __shfl_xor_sync(0xffffffffu, a, 4);
        bb += __shfl_xor_sync(0xffffffffu, bb, 4);
        c  += __shfl_xor_sync(0xffffffffu, c, 4);
        const int g2 = (lane >> 2) & 3;
        float x = (g2 == 0) ? a : (g2 == 1) ? bb : c;
        x += __shfl_xor_sync(0xffffffffu, x, 2);
        x += __shfl_xor_sync(0xffffffffu, x, 1);
        if ((lane & 3) == 0 && g2 < 3 && r < NROWS)
            scal_s[r * 4 + g2] = x;
    }
    __syncthreads();

    // ---- softmax + weighted scalar reductions (warp 0) ----
    if (wid == 0) {
        const float src_sq = scal_s[60 * 4 + 0];
        const float tar_sq = scal_s[61 * 4 + 0];
        const float delta  = delta_w[sidx];
        const float ttime  = t_times[b];

        float logit[2], pal[2], dm[2];
        float m = -1e30f;
#pragma unroll
        for (int k = 0; k < 2; k++) {
            const int h = lane + 32 * k;
            if (h < NH) {
                const float hh = scal_s[h * 4 + 0];
                logit[k] = -(src_sq + hh - 2.0f * scal_s[h * 4 + 1]);
                pal[k]   = -(tar_sq + hh - 2.0f * scal_s[h * 4 + 2]);
                const float dt = fabsf(ttime - h_times[b * NH + h]);
                dm[k] = __expf(delta * dt) * h_mask[b * NH + h];
                m = fmaxf(m, logit[k]);
            }
        }
        m = wredmax(m);

        float S = 0.f, Wn = 0.f, Cn = 0.f, Pn = 0.f;
#pragma unroll
        for (int k = 0; k < 2; k++) {
            const int h = lane + 32 * k;
            if (h < NH) {
                const float e = __expf(logit[k] - m);
                const float w = e * dm[k];
                w_s[h] = w;
                S  += e;
                Wn += w;
                Cn += w * scal_s[h * 4 + 0];
                Pn += w * pal[k];
            }
        }
        S  += __shfl_xor_sync(0xffffffffu, S, 16);
        Wn += __shfl_xor_sync(0xffffffffu, Wn, 16);
        Cn += __shfl_xor_sync(0xffffffffu, Cn, 16);
        Pn += __shfl_xor_sync(0xffffffffu, Pn, 16);
        S  += __shfl_xor_sync(0xffffffffu, S, 8);
        Wn += __shfl_xor_sync(0xffffffffu, Wn, 8);
        Cn += __shfl_xor_sync(0xffffffffu, Cn, 8);
        Pn += __shfl_xor_sync(0xffffffffu, Pn, 8);
        const int g = lane >> 3;
        float x = (g == 0) ? S : (g == 1) ? Wn : (g == 2) ? Cn : Pn;
        x += __shfl_xor_sync(0xffffffffu, x, 4);
        x += __shfl_xor_sync(0xffffffffu, x, 2);
        x += __shfl_xor_sync(0xffffffffu, x, 1);
        const float Sv = __shfl_sync(0xffffffffu, x, 0);
        if (lane == 8)  sc[0] = x / Sv;      // W
        if (lane == 16) sc[1] = x / Sv;      // C
        if (lane == 24) sc[2] = x / Sv;      // P
        if (lane == 0)  sc[3] = 1.0f / Sv;   // invS
    }
    __syncthreads();

    // ---- hbar partials: warp-per-row float4 re-read (L1/L2-hot, LDG.128) ----
    {
        float4 acc = make_float4(0.f, 0.f, 0.f, 0.f);
#pragma unroll
        for (int i = 0; i < 7; i++) {
            const int h = wid + i * NWARP;
            if (h < NH) {
                const float w = w_s[h];
                const float4 v = emb4[(size_t)idx_s[h] * EV4 + lane];
                acc.x += w * v.x; acc.y += w * v.y;
                acc.z += w * v.z; acc.w += w * v.w;
            }
        }
        hb_p[wid * 32 + lane] = acc;
    }
    __syncthreads();

    // ---- tail: combine hbar + per-negative hbar.n + log-sigmoid ----
    {
        float4 hb4 = make_float4(0.f, 0.f, 0.f, 0.f);
#pragma unroll
        for (int g = 0; g < NWARP; g++) {
            const float4 p = hb_p[g * 32 + lane];
            hb4.x += p.x; hb4.y += p.y; hb4.z += p.z; hb4.w += p.w;
        }

        const float Wv = sc[0], Cv = sc[1], invS = sc[3];
        const float ss = scal_s[60 * 4 + 0];

        {
            const int n = wid;
            const float4 ng = emb4[(size_t)idx_s[50 + n] * EV4 + lane];
            float hn = wredsum(dot4(hb4, ng));
            if (lane == 0) {
                const float nn = scal_s[(50 + n) * 4 + 0];
                const float sn = scal_s[(50 + n) * 4 + 1];
                const float n_mu = -(ss + nn - 2.0f * sn);
                const float nl   = n_mu - Cv - Wv * nn + 2.0f * invS * hn;
                nterm_s[n] = __logf(1.0f / (1.0f + __expf(nl)) + EPS);
            }
        }
        if (wid < NNEG - NWARP) {
            const int n = NWARP + wid;
            const float4 ng = emb4[(size_t)idx_s[50 + n] * EV4 + lane];
            float hn = wredsum(dot4(hb4, ng));
            if (lane == 0) {
                const float nn = scal_s[(50 + n) * 4 + 0];
                const float sn = scal_s[(50 + n) * 4 + 1];
                const float n_mu = -(ss + nn - 2.0f * sn);
                const float nl   = n_mu - Cv - Wv * nn + 2.0f * invS * hn;
                nterm_s[n] = __logf(1.0f / (1.0f + __expf(nl)) + EPS);
            }
        }
    }
    __syncthreads();

    if (tid == 0) {
        const float ss = scal_s[60 * 4 + 0];
        const float st = scal_s[60 * 4 + 2];
        const float tt = scal_s[61 * 4 + 0];
        const float p_mu     = -(ss + tt - 2.0f * st);
        const float p_lambda = p_mu + sc[2];
        const float pos_loss = -__logf(1.0f / (1.0f + __expf(-p_lambda)) + EPS);
        float neg_loss = 0.f;
#pragma unroll
        for (int n = 0; n < NNEG; n++) neg_loss += nterm_s[n];
        out[b] = pos_loss - neg_loss;
    }
}

extern "C" void kernel_launch(void* const* d_in, const int* in_sizes, int n_in,
                              void* d_out, int out_size)
{
    const int*   s_nodes = (const int*)  d_in[0];
    const int*   t_nodes = (const int*)  d_in[1];
    const float* t_times = (const float*)d_in[2];
    const int*   h_nodes = (const int*)  d_in[3];
    const float* h_times = (const float*)d_in[4];
    const float* h_mask  = (const float*)d_in[5];
    const int*   n_nodes = (const int*)  d_in[6];
    const float* emb     = (const float*)d_in[7];
    const float* delta_w = (const float*)d_in[8];
    float*       out     = (float*)d_out;

    const int B = in_sizes[0];
    htne_kernel<<<B, NTHR>>>(s_nodes, t_nodes, t_times, h_nodes, h_times,
                             h_mask, n_nodes, emb, delta_w, out);
}